// round 16
// baseline (speedup 1.0000x reference)
#include <cuda_runtime.h>
#include <cuda_fp16.h>
#include <math.h>

// ---------------- problem constants ----------------
#define NN    8192
#define EE    262144
#define HID   128
#define NRBF  50
#define K1    64
#define NLAY  6
#define PR    72           // smem pitch (fp16) for rbf / W1^T
#define PT    136          // smem pitch (fp16) for T / W2^T / node tiles
#define PG    132          // smem pitch (fp16) for F in edge kernel
#define NSLOT 20

typedef __half  h16;
typedef __half2 h162;

// ---------------- device scratch ----------------
__device__ __align__(16) h16 g_rbf[(size_t)EE * K1];
__device__ __align__(16) h16 g_w1t[NLAY * HID * K1];
__device__ __align__(16) h16 g_w2t[NLAY * HID * HID];
__device__ __align__(16) h16 g_npt[HID * K1];
__device__ __align__(16) h16 g_nwt[NSLOT * HID * HID];
__device__ __align__(16) h16 g_h16 [NN * HID];
__device__ __align__(16) h16 g_nex16[NN * HID];
__device__ float g_cut[EE];
__device__ float g_cutm[EE];
__device__ int   g_srow[EE];
__device__ int   g_sdst[EE];
__device__ int   g_perm[EE];
__device__ int   g_cnt[NN];
__device__ int   g_offm[NN];
__device__ float g_x  [NN * HID];
__device__ float g_agg[NN * HID];

// ---------------- small helper kernels ----------------
__global__ void k_zero_cnt() {
    int i = blockIdx.x * blockDim.x + threadIdx.x;
    if (i < NN) g_cnt[i] = 0;
}

__global__ void k_hist(const int* __restrict__ ei) {
    int e = blockIdx.x * blockDim.x + threadIdx.x;
    if (e < EE) atomicAdd(&g_cnt[ei[EE + e]], 1);
}

__global__ void k_scan() {
    __shared__ int part[1024];
    int t = threadIdx.x;
    int base = t * 8;
    int loc[8];
    int s = 0;
#pragma unroll
    for (int i = 0; i < 8; i++) { loc[i] = s; s += g_cnt[base + i]; }
    part[t] = s;
    __syncthreads();
    int val = s;
    for (int off = 1; off < 1024; off <<= 1) {
        int v = (t >= off) ? part[t - off] : 0;
        __syncthreads();
        val += v;
        part[t] = val;
        __syncthreads();
    }
    int pre = (t == 0) ? 0 : part[t - 1];
#pragma unroll
    for (int i = 0; i < 8; i++) g_offm[base + i] = pre + loc[i];
}

__global__ void k_place(const int* __restrict__ ei) {
    int e = blockIdx.x * blockDim.x + threadIdx.x;
    if (e < EE) {
        int c = ei[EE + e];
        int p = atomicAdd(&g_offm[c], 1);
        g_perm[p] = e;
    }
}

__global__ void k_build(const int* __restrict__ ei, const float* __restrict__ ew,
                        const float* __restrict__ means, const float* __restrict__ betas) {
    int warp = (blockIdx.x * blockDim.x + threadIdx.x) >> 5;
    int lane = threadIdx.x & 31;
    if (warp >= EE) return;
    int e = g_perm[warp];
    int r = ei[e];
    int c = ei[EE + e];
    float d = ew[e];
    float cut = 0.5f * (cosf(d * 0.628318530717958647692f) + 1.0f);
    if (!(d < 5.0f)) cut = 0.f;
    float ex = __expf(-d);
    size_t ro = (size_t)warp * K1;
    {
        float m = means[lane], b = betas[lane];
        float v = ex - m;
        g_rbf[ro + lane] = __float2half_rn(cut * __expf(-b * v * v));
    }
    int k2 = lane + 32;
    float val2 = 0.f;
    if (k2 < NRBF) {
        float m = means[k2], b = betas[k2];
        float v = ex - m;
        val2 = cut * __expf(-b * v * v);
    }
    g_rbf[ro + k2] = __float2half_rn(val2);
    if (lane == 0) {
        g_cut[warp]  = cut;
        g_cutm[warp] = (r != c) ? cut : 0.f;
        g_srow[warp] = r;
        g_sdst[warp] = c;
    }
}

__global__ void k_gather(const int* __restrict__ z, const float* __restrict__ emb,
                         const float* __restrict__ neemb) {
    int i = blockIdx.x * blockDim.x + threadIdx.x;
    if (i >= NN * HID) return;
    int n = i >> 7, c = i & 127;
    int zi = z[n];
    g_x[i]     = emb[zi * HID + c];
    g_nex16[i] = __float2half_rn(neemb[zi * HID + c]);
    g_agg[i]   = 0.f;
}

// weight prep (single fp16, transposed)
__global__ void k_wprep1(const float* __restrict__ w, int mode, int layers) {
    int i = blockIdx.x * blockDim.x + threadIdx.x;
    if (i >= layers * HID * K1) return;
    int k = i & (K1 - 1);
    int n = (i >> 6) & (HID - 1);
    int l = i >> 13;
    float v = (k < NRBF) ? w[((size_t)l * NRBF + k) * HID + n] : 0.f;
    if (mode == 0) g_w1t[i] = __float2half_rn(v);
    else           g_npt[i] = __float2half_rn(v);
}

__global__ void k_wprep2(const float* __restrict__ w) {
    int i = blockIdx.x * blockDim.x + threadIdx.x;
    if (i >= NLAY * HID * HID) return;
    int k = i & (HID - 1);
    int n = (i >> 7) & (HID - 1);
    int l = i >> 14;
    g_w2t[i] = __float2half_rn(w[((size_t)l * HID + k) * HID + n]);
}

__global__ void k_wprepAll(const float* __restrict__ necatw, const float* __restrict__ lin1w,
                           const float* __restrict__ lin2w, const float* __restrict__ linw) {
    int slot = blockIdx.x >> 6;
    int i = (blockIdx.x & 63) * 256 + threadIdx.x;
    const float* src;
    if (slot < 2)       src = necatw + (size_t)slot * HID * HID;
    else if (slot < 8)  src = lin1w + (size_t)(slot - 2) * HID * HID;
    else if (slot < 14) src = lin2w + (size_t)(slot - 8) * HID * HID;
    else                src = linw  + (size_t)(slot - 14) * HID * HID;
    int k = i & (HID - 1);
    int n = i >> 7;
    g_nwt[(size_t)slot * HID * HID + i] = __float2half_rn(src[k * HID + n]);
}

// ---------------- warp-MMA helpers (fp16) ----------------
__device__ __forceinline__ void mma16816(float c[4], const unsigned a[4], const unsigned b[2]) {
    asm volatile(
        "mma.sync.aligned.m16n8k16.row.col.f32.f16.f16.f32 "
        "{%0,%1,%2,%3}, {%4,%5,%6,%7}, {%8,%9}, {%0,%1,%2,%3};\n"
        : "+f"(c[0]), "+f"(c[1]), "+f"(c[2]), "+f"(c[3])
        : "r"(a[0]), "r"(a[1]), "r"(a[2]), "r"(a[3]), "r"(b[0]), "r"(b[1]));
}

__device__ __forceinline__ void ldsm4(unsigned r[4], unsigned addr) {
    asm volatile("ldmatrix.sync.aligned.m8n8.x4.shared.b16 {%0,%1,%2,%3}, [%4];"
        : "=r"(r[0]), "=r"(r[1]), "=r"(r[2]), "=r"(r[3]) : "r"(addr));
}

__device__ __forceinline__ unsigned a_addr(unsigned base, int m0, int PB, int lane) {
    int sel = lane >> 3, li = lane & 7;
    return base + (m0 + li + (sel & 1) * 8) * PB + ((sel >> 1) * 8) * 2;
}
__device__ __forceinline__ unsigned b_addr(unsigned base, int n0, int PB, int lane) {
    int sel = lane >> 3, li = lane & 7;
    return base + (n0 + li + (sel >> 1) * 8) * PB + ((sel & 1) * 8) * 2;
}

// 32x32 warp GEMM (node kernels): acc += A*B, single fp16
template <int KSTEPS, int PB>
__device__ __forceinline__ void wgemm1(unsigned aA, unsigned bB, float acc[2][4][4]) {
#pragma unroll
    for (int ks = 0; ks < KSTEPS; ks++) {
        unsigned off = ks * 32;
        unsigned a0[4], a1[4], b0[4], b1[4];
        ldsm4(a0, aA + off);
        ldsm4(a1, aA + 16 * PB + off);
        ldsm4(b0, bB + off);
        ldsm4(b1, bB + 16 * PB + off);
#pragma unroll
        for (int nt = 0; nt < 4; nt++) {
            const unsigned* bp = (nt < 2) ? (b0 + 2 * nt) : (b1 + 2 * (nt - 2));
            mma16816(acc[0][nt], a0, bp);
            mma16816(acc[1][nt], a1, bp);
        }
    }
}

// 32x64 warp GEMM (edge kernel): acc += A*B, single fp16
template <int KSTEPS, int PB>
__device__ __forceinline__ void wgemm64(unsigned aA, unsigned bB, float acc[2][8][4]) {
#pragma unroll
    for (int ks = 0; ks < KSTEPS; ks++) {
        unsigned off = ks * 32;
        unsigned a0[4], a1[4];
        ldsm4(a0, aA + off);
        ldsm4(a1, aA + 16 * PB + off);
#pragma unroll
        for (int half = 0; half < 2; half++) {
            unsigned hb = half * 32 * PB;
            unsigned b0[4], b1[4];
            ldsm4(b0, bB + hb + off);
            ldsm4(b1, bB + hb + 16 * PB + off);
#pragma unroll
            for (int q = 0; q < 4; q++) {
                int nt = half * 4 + q;
                const unsigned* bp = (q < 2) ? (b0 + 2 * q) : (b1 + 2 * (q - 2));
                mma16816(acc[0][nt], a0, bp);
                mma16816(acc[1][nt], a1, bp);
            }
        }
    }
}

// ---------------- cp.async helpers ----------------
__device__ __forceinline__ void cpa16(unsigned saddr, const void* gaddr) {
    asm volatile("cp.async.ca.shared.global [%0], [%1], 16;" :: "r"(saddr), "l"(gaddr));
}
__device__ __forceinline__ void cpa_commit() { asm volatile("cp.async.commit_group;"); }
__device__ __forceinline__ void cpa_wait0()  { asm volatile("cp.async.wait_group 0;"); }

__device__ __forceinline__ float fsilu(float x) {
    return __fdividef(x, 1.f + __expf(-x));
}

// ---------------- fused edge MLP + segmented aggregation (persistent, occ>=2)
// 256 threads, 8 warps (32x64 tiles each, 4m x 2n).
// interaction smem: T/F[0,34816) W2[34816,+34816) rbf[69632,+18432)
//   W1[88064,+18432) misc[106496,+4096) = 110592 -> occupancy 2
// NE smem: F[0,34816) rbf[34816,+18432) W1[53248,+18432) misc[71680,+4096)
//   = 75776 -> occupancy 3
template <int NE>
__global__ void __launch_bounds__(256, 1)
k_edge(int layer, const float* __restrict__ b1g, const float* __restrict__ b2g) {
    extern __shared__ __align__(16) char smref[];
    const int OFF_TF   = 0;
    const int OFF_W2   = 34816;              // interaction only
    const int OFF_R    = NE ? 34816 : 69632;
    const int OFF_W1   = OFF_R + 18432;
    const int OFF_MISC = NE ? 71680 : 106496;
    const int OFF_CUT  = OFF_MISC;          // [2][128] f32
    const int OFF_ROW  = OFF_MISC + 1024;   // [2][128] i32
    const int OFF_DST  = OFF_MISC + 2048;   // [2][128] i32
    const int OFF_B1   = OFF_MISC + 3072;
    const int OFF_B2   = OFF_MISC + 3584;

    h16*  sT   = (h16*)(smref + OFF_TF);    // T (pitch PT) and F (pitch PG) overlay
    h16*  sF16 = (h16*)(smref + OFF_TF);
    float* sB1 = (float*)(smref + OFF_B1);
    float* sB2 = (float*)(smref + OFF_B2);

    int tid = threadIdx.x;
    unsigned sbase = (unsigned)__cvta_generic_to_shared(smref);

    const long NT = EE / 128;
    long tile = blockIdx.x;
    int buf = 0;

    // issue tile-0 rbf + metadata copy
    if (tile < NT) {
        long ebase = tile * 128;
        for (int c = tid; c < 1024; c += 256) {
            int r = c >> 3, ch = c & 7;
            cpa16(sbase + OFF_R + r * (PR * 2) + ch * 16, &g_rbf[(ebase + r) * K1 + ch * 8]);
        }
        if (tid < 32) {
            const float* cs = NE ? g_cutm : g_cut;
            cpa16(sbase + OFF_CUT + tid * 16, cs + ebase + tid * 4);
        } else if (tid < 64) {
            int t = tid - 32;
            cpa16(sbase + OFF_ROW + t * 16, g_srow + ebase + t * 4);
        } else if (tid < 96) {
            int t = tid - 64;
            cpa16(sbase + OFF_DST + t * 16, g_sdst + ebase + t * 4);
        }
    }
    cpa_commit();

    // ---- stage weights once (single fp16) ----
    {
        const unsigned* gw = (const unsigned*)(NE ? g_npt : (g_w1t + (size_t)layer * HID * K1));
        unsigned* sw = (unsigned*)(smref + OFF_W1);
        for (int i = tid; i < 128 * 32; i += 256) {
            int r = i >> 5, wd = i & 31;
            sw[r * (PR / 2) + wd] = gw[i];
        }
    }
    if (!NE) {
        const unsigned* gw = (const unsigned*)(g_w2t + (size_t)layer * HID * HID);
        unsigned* sw = (unsigned*)(smref + OFF_W2);
        for (int i = tid; i < 128 * 64; i += 256) {
            int r = i >> 6, wd = i & 63;
            sw[r * (PT / 2) + wd] = gw[i];
        }
    }
    if (tid < 128) {
        sB1[tid] = b1g[tid];
        sB2[tid] = NE ? 0.f : b2g[tid];
    }

    int w = tid >> 5, lane = tid & 31;
    int m0 = (w & 3) * 32, n0 = (w >> 2) * 64;
    int g = lane >> 2, tc = lane & 3;

    unsigned g1a = a_addr(sbase + OFF_R,  m0, PR * 2, lane);
    unsigned g1b = b_addr(sbase + OFF_W1, n0, PR * 2, lane);
    unsigned g2a = a_addr(sbase + OFF_TF, m0, PT * 2, lane);
    unsigned g2b = b_addr(sbase + OFF_W2, n0, PT * 2, lane);

    const h16* hsrc = NE ? g_nex16 : g_h16;

    for (; tile < NT; tile += gridDim.x, buf ^= 1) {
        cpa_wait0();
        __syncthreads();   // rbf + meta[buf] ready; prev tile's F consumed

        float* sCut = (float*)(smref + OFF_CUT + buf * 512);
        int*   sRow = (int*)(smref + OFF_ROW + buf * 512);
        int*   sDst = (int*)(smref + OFF_DST + buf * 512);

        // ---- GEMM1: rbf[128,64] @ W1[64,128] ----
        {
            float acc[2][8][4];
#pragma unroll
            for (int a = 0; a < 2; a++)
#pragma unroll
                for (int b = 0; b < 8; b++)
#pragma unroll
                    for (int c = 0; c < 4; c++) acc[a][b][c] = 0.f;
            wgemm64<K1 / 16, PR * 2>(g1a, g1b, acc);

            if (NE) {
                // F = (acc + b1) * cutm -> fp16 (pitch PG)
#pragma unroll
                for (int mt = 0; mt < 2; mt++) {
                    int ra = m0 + mt * 16 + g, rb2 = ra + 8;
                    float cua = sCut[ra], cub = sCut[rb2];
#pragma unroll
                    for (int nt = 0; nt < 8; nt++) {
                        int col = n0 + nt * 8 + 2 * tc;
                        *(h162*)&sF16[ra * PG + col] = __floats2half2_rn(
                            (acc[mt][nt][0] + sB1[col]) * cua,
                            (acc[mt][nt][1] + sB1[col + 1]) * cua);
                        *(h162*)&sF16[rb2 * PG + col] = __floats2half2_rn(
                            (acc[mt][nt][2] + sB1[col]) * cub,
                            (acc[mt][nt][3] + sB1[col + 1]) * cub);
                    }
                }
            } else {
                // T = silu(acc + b1) -> fp16 (pitch PT)
#pragma unroll
                for (int mt = 0; mt < 2; mt++) {
                    int ra = m0 + mt * 16 + g, rb2 = ra + 8;
#pragma unroll
                    for (int nt = 0; nt < 8; nt++) {
                        int col = n0 + nt * 8 + 2 * tc;
                        float x0 = fsilu(acc[mt][nt][0] + sB1[col]);
                        float x1 = fsilu(acc[mt][nt][1] + sB1[col + 1]);
                        float x2 = fsilu(acc[mt][nt][2] + sB1[col]);
                        float x3 = fsilu(acc[mt][nt][3] + sB1[col + 1]);
                        *(h162*)&sT[ra * PT + col]  = __floats2half2_rn(x0, x1);
                        *(h162*)&sT[rb2 * PT + col] = __floats2half2_rn(x2, x3);
                    }
                }
            }
        }
        __syncthreads();   // rbf dead; T (or F) visible

        // ---- issue next tile's rbf + metadata ----
        {
            long nxt = tile + gridDim.x;
            if (nxt < NT) {
                long ebase = nxt * 128;
                int nb = buf ^ 1;
                for (int c = tid; c < 1024; c += 256) {
                    int r = c >> 3, ch = c & 7;
                    cpa16(sbase + OFF_R + r * (PR * 2) + ch * 16,
                          &g_rbf[(ebase + r) * K1 + ch * 8]);
                }
                if (tid < 32) {
                    const float* cs = NE ? g_cutm : g_cut;
                    cpa16(sbase + OFF_CUT + nb * 512 + tid * 16, cs + ebase + tid * 4);
                } else if (tid < 64) {
                    int t = tid - 32;
                    cpa16(sbase + OFF_ROW + nb * 512 + t * 16, g_srow + ebase + t * 4);
                } else if (tid < 96) {
                    int t = tid - 64;
                    cpa16(sbase + OFF_DST + nb * 512 + t * 16, g_sdst + ebase + t * 4);
                }
            }
            cpa_commit();
        }

        // ---- GEMM2 (interaction only): T @ W2 -> F overlays T ----
        if (!NE) {
            float acc[2][8][4];
#pragma unroll
            for (int a = 0; a < 2; a++)
#pragma unroll
                for (int b = 0; b < 8; b++)
#pragma unroll
                    for (int c = 0; c < 4; c++) acc[a][b][c] = 0.f;
            wgemm64<HID / 16, PT * 2>(g2a, g2b, acc);
            __syncthreads();   // all T reads done before F overwrite

#pragma unroll
            for (int mt = 0; mt < 2; mt++) {
                int ra = m0 + mt * 16 + g, rb2 = ra + 8;
                float cua = sCut[ra], cub = sCut[rb2];
#pragma unroll
                for (int nt = 0; nt < 8; nt++) {
                    int col = n0 + nt * 8 + 2 * tc;
                    *(h162*)&sF16[ra * PG + col] = __floats2half2_rn(
                        (acc[mt][nt][0] + sB2[col]) * cua,
                        (acc[mt][nt][1] + sB2[col + 1]) * cua);
                    *(h162*)&sF16[rb2 * PG + col] = __floats2half2_rn(
                        (acc[mt][nt][2] + sB2[col]) * cub,
                        (acc[mt][nt][3] + sB2[col + 1]) * cub);
                }
            }
            __syncthreads();   // F visible
        }

        // ---- aggregation: 4 groups x 64 threads, channel pair, 32 edges ----
        int grp = tid >> 6;
        int f2 = tid & 63;
        int c0 = 2 * f2;
        int e0 = grp * 32;
        float a0 = 0.f, a1 = 0.f;
        int cur = sDst[e0];
#pragma unroll 1
        for (int b = 0; b < 4; b++) {
            h162 hb[8];
#pragma unroll
            for (int j = 0; j < 8; j++)
                hb[j] = *(const h162*)&hsrc[(long)sRow[e0 + b * 8 + j] * HID + c0];
#pragma unroll
            for (int j = 0; j < 8; j++) {
                int e = e0 + b * 8 + j;
                int dd = sDst[e];
                if (dd != cur) {
                    atomicAdd(&g_agg[(long)cur * HID + c0], a0);
                    atomicAdd(&g_agg[(long)cur * HID + c0 + 1], a1);
                    a0 = a1 = 0.f;
                    cur = dd;
                }
                float2 hf = __half22float2(hb[j]);
                float2 ff = __half22float2(*(const h162*)&sF16[e * PG + c0]);
                a0 = fmaf(hf.x, ff.x, a0);
                a1 = fmaf(hf.y, ff.y, a1);
            }
        }
        atomicAdd(&g_agg[(long)cur * HID + c0], a0);
        atomicAdd(&g_agg[(long)cur * HID + c0 + 1], a1);
    }
}

// ---------------- node-kernel shared pieces (R14, unchanged) -----------------
#define NA_BYTES  (64 * PT * 2)
#define NW_BYTES  (HID * PT * 2)
#define NOFF_A    0
#define NOFF_WA   NA_BYTES
#define NOFF_WB   (NOFF_WA + NW_BYTES)
#define NOFF_H    (NOFF_WB + NW_BYTES)
#define NOFF_B    (NOFF_H + NA_BYTES)
#define NSM_TOTAL (NOFF_B + 1024)

__device__ __forceinline__ void stageA_f16(char* smref, int off, const float* src,
                                           int rb, int tid) {
    h16* dst = (h16*)(smref + off);
    for (int i = tid; i < 64 * HID; i += 256) {
        int r = i >> 7, k = i & 127;
        dst[r * PT + k] = __float2half_rn(src[(long)(rb + r) * HID + k]);
    }
}

__device__ __forceinline__ void stageW(char* smref, int off, int slot, int tid) {
    const unsigned* gw = (const unsigned*)(g_nwt + (size_t)slot * HID * HID);
    unsigned* sw = (unsigned*)(smref + off);
    for (int i = tid; i < 128 * 64; i += 256) {
        int r = i >> 6, wd = i & 63;
        sw[r * (PT / 2) + wd] = gw[i];
    }
}

__global__ void __launch_bounds__(256, 1)
k_nodeNE(const float* __restrict__ necatb) {
    extern __shared__ __align__(16) char smref[];
    float* sBa = (float*)(smref + NOFF_B);

    int tid = threadIdx.x;
    int rb = blockIdx.x * 64;
    unsigned sbase = (unsigned)__cvta_generic_to_shared(smref);

    stageA_f16(smref, NOFF_A, g_x, rb, tid);
    stageW(smref, NOFF_WA, 0, tid);
    stageW(smref, NOFF_WB, 1, tid);
    if (tid < 128) sBa[tid] = necatb[tid];
    __syncthreads();

    int w = tid >> 5, lane = tid & 31;
    int m0 = (w & 1) * 32, n0 = (w >> 1) * 32;
    int g = lane >> 2, tc = lane & 3;

    float acc[2][4][4];
#pragma unroll
    for (int a = 0; a < 2; a++)
#pragma unroll
        for (int b = 0; b < 4; b++)
#pragma unroll
            for (int c = 0; c < 4; c++) acc[a][b][c] = 0.f;

    {
        unsigned aA = a_addr(sbase + NOFF_A, m0, PT * 2, lane);
        unsigned bB = b_addr(sbase + NOFF_WA, n0, PT * 2, lane);
        wgemm1<HID / 16, PT * 2>(aA, bB, acc);
    }
    __syncthreads();

    stageA_f16(smref, NOFF_A, g_agg, rb, tid);
    stageW(smref, NOFF_WA, 2, tid);
    __syncthreads();

    {
        float4* za = (float4*)(g_agg + (long)rb * HID);
        for (int i = tid; i < 64 * HID / 4; i += 256) za[i] = make_float4(0.f, 0.f, 0.f, 0.f);
    }

    {
        unsigned aA = a_addr(sbase + NOFF_A, m0, PT * 2, lane);
        unsigned bB = b_addr(sbase + NOFF_WB, n0, PT * 2, lane);
        wgemm1<HID / 16, PT * 2>(aA, bB, acc);

        h16* xh = (h16*)(smref + NOFF_H);
#pragma unroll
        for (int mt = 0; mt < 2; mt++) {
#pragma unroll
            for (int dr = 0; dr < 2; dr++) {
                int r = m0 + mt * 16 + g + dr * 8;
                long ro = (long)(rb + r) * HID;
#pragma unroll
                for (int nt = 0; nt < 4; nt++) {
                    int col = n0 + nt * 8 + 2 * tc;
                    float v0 = acc[mt][nt][2 * dr]     + sBa[col];
                    float v1 = acc[mt][nt][2 * dr + 1] + sBa[col + 1];
                    *(float2*)&g_x[ro + col] = make_float2(v0, v1);
                    *(h162*)&xh[r * PT + col] = __floats2half2_rn(v0, v1);
                }
            }
        }
    }
    __syncthreads();

    {
        float acc2[2][4][4];
#pragma unroll
        for (int a = 0; a < 2; a++)
#pragma unroll
            for (int b = 0; b < 4; b++)
#pragma unroll
                for (int c = 0; c < 4; c++) acc2[a][b][c] = 0.f;
        unsigned aA = a_addr(sbase + NOFF_H, m0, PT * 2, lane);
        unsigned bB = b_addr(sbase + NOFF_WA, n0, PT * 2, lane);
        wgemm1<HID / 16, PT * 2>(aA, bB, acc2);
#pragma unroll
        for (int mt = 0; mt < 2; mt++) {
#pragma unroll
            for (int dr = 0; dr < 2; dr++) {
                int r = m0 + mt * 16 + g + dr * 8;
                long ro = (long)(rb + r) * HID;
#pragma unroll
                for (int nt = 0; nt < 4; nt++) {
                    int col = n0 + nt * 8 + 2 * tc;
                    *(h162*)&g_h16[ro + col] =
                        __floats2half2_rn(acc2[mt][nt][2 * dr], acc2[mt][nt][2 * dr + 1]);
                }
            }
        }
    }
}

__global__ void __launch_bounds__(256, 1)
k_nodeL(int l, int last, const float* __restrict__ b2g, const float* __restrict__ b3g,
        float* dout) {
    extern __shared__ __align__(16) char smref[];
    float* sB2 = (float*)(smref + NOFF_B);
    float* sB3 = sB2 + 128;

    int tid = threadIdx.x;
    int rb = blockIdx.x * 64;
    unsigned sbase = (unsigned)__cvta_generic_to_shared(smref);

    stageA_f16(smref, NOFF_A, g_agg, rb, tid);
    stageW(smref, NOFF_WA, 8 + l, tid);
    stageW(smref, NOFF_WB, 14 + l, tid);
    if (tid < 128) { sB2[tid] = b2g[tid]; sB3[tid] = b3g[tid]; }
    __syncthreads();

    int w = tid >> 5, lane = tid & 31;
    int m0 = (w & 1) * 32, n0 = (w >> 1) * 32;
    int g = lane >> 2, tc = lane & 3;

    {
        float acc[2][4][4];
#pragma unroll
        for (int a = 0; a < 2; a++)
#pragma unroll
            for (int b = 0; b < 4; b++)
#pragma unroll
                for (int c = 0; c < 4; c++) acc[a][b][c] = 0.f;
        unsigned aA = a_addr(sbase + NOFF_A, m0, PT * 2, lane);
        unsigned bB = b_addr(sbase + NOFF_WA, n0, PT * 2, lane);
        wgemm1<HID / 16, PT * 2>(aA, bB, acc);

        h16* sHn = (h16*)(smref + NOFF_H);
#pragma unroll
        for (int mt = 0; mt < 2; mt++) {
            int ra = m0 + mt * 16 + g, rb2 = ra + 8;
#pragma unroll
            for (int nt = 0; nt < 4; nt++) {
                int col = n0 + nt * 8 + 2 * tc;
                float x0 = fsilu(acc[mt][nt][0] + sB2[col]);
                float x1 = fsilu(acc[mt][nt][1] + sB2[col + 1]);
                float x2 = fsilu(acc[mt][nt][2] + sB2[col]);
                float x3 = fsilu(acc[mt][nt][3] + sB2[col + 1]);
                *(h162*)&sHn[ra * PT + col]  = __floats2half2_rn(x0, x1);
                *(h162*)&sHn[rb2 * PT + col] = __floats2half2_rn(x2, x3);
            }
        }
    }
    __syncthreads();

    if (!last) {
        stageW(smref, NOFF_WA, 2 + (l + 1), tid);
        float4* za = (float4*)(g_agg + (long)rb * HID);
        for (int i = tid; i < 64 * HID / 4; i += 256) za[i] = make_float4(0.f, 0.f, 0.f, 0.f);
    }

    {
        float acc[2][4][4];
#pragma unroll
        for (int a = 0; a < 2; a++)
#pragma unroll
            for (int b = 0; b < 4; b++)
#pragma unroll
                for (int c = 0; c < 4; c++) acc[a][b][c] = 0.f;
        unsigned aA = a_addr(sbase + NOFF_H, m0, PT * 2, lane);
        unsigned bB = b_addr(sbase + NOFF_WB, n0, PT * 2, lane);
        wgemm1<HID / 16, PT * 2>(aA, bB, acc);

        float* out = last ? dout : g_x;
        h16* xh = (h16*)(smref + NOFF_A);
#pragma unroll
        for (int mt = 0; mt < 2; mt++) {
#pragma unroll
            for (int dr = 0; dr < 2; dr++) {
                int r = m0 + mt * 16 + g + dr * 8;
                long ro = (long)(rb + r) * HID;
#pragma unroll
                for (int nt = 0; nt < 4; nt++) {
                    int col = n0 + nt * 8 + 2 * tc;
                    float v0 = acc[mt][nt][2 * dr]     + sB3[col] + g_x[ro + col];
                    float v1 = acc[mt][nt][2 * dr + 1] + sB3[col + 1] + g_x[ro + col + 1];
                    *(float2*)&out[ro + col] = make_float2(v0, v1);
                    if (!last)
                        *(h162*)&xh[r * PT + col] = __floats2half2_rn(v0, v1);
                }
            }
        }
    }
    if (last) return;
    __syncthreads();

    {
        float acc[2][4][4];
#pragma unroll
        for (int a = 0; a < 2; a++)
#pragma unroll
            for (int b = 0; b < 4; b++)
#pragma unroll
                for (int c = 0; c < 4; c++) acc[a][b][c] = 0.f;
        unsigned aA = a_addr(sbase + NOFF_A, m0, PT * 2, lane);
        unsigned bB = b_addr(sbase + NOFF_WA, n0, PT * 2, lane);
        wgemm1<HID / 16, PT * 2>(aA, bB, acc);
#pragma unroll
        for (int mt = 0; mt < 2; mt++) {
#pragma unroll
            for (int dr = 0; dr < 2; dr++) {
                int r = m0 + mt * 16 + g + dr * 8;
                long ro = (long)(rb + r) * HID;
#pragma unroll
                for (int nt = 0; nt < 4; nt++) {
                    int col = n0 + nt * 8 + 2 * tc;
                    *(h162*)&g_h16[ro + col] =
                        __floats2half2_rn(acc[mt][nt][2 * dr], acc[mt][nt][2 * dr + 1]);
                }
            }
        }
    }
}

// ---------------- launch ----------------
extern "C" void kernel_launch(void* const* d_in, const int* in_sizes, int n_in,
                              void* d_out, int out_size) {
    const int*   z       = (const int*)d_in[0];
    const int*   ei      = (const int*)d_in[1];
    const float* ew      = (const float*)d_in[2];
    const float* emb     = (const float*)d_in[3];
    const float* neemb   = (const float*)d_in[4];
    const float* neprojw = (const float*)d_in[5];
    const float* neprojb = (const float*)d_in[6];
    const float* necatw  = (const float*)d_in[7];
    const float* necatb  = (const float*)d_in[8];
    const float* means   = (const float*)d_in[9];
    const float* betas   = (const float*)d_in[10];
    const float* mlpw1   = (const float*)d_in[11];
    const float* mlpb1   = (const float*)d_in[12];
    const float* mlpw2   = (const float*)d_in[13];
    const float* mlpb2   = (const float*)d_in[14];
    const float* lin1w   = (const float*)d_in[15];
    const float* lin2w   = (const float*)d_in[16];
    const float* lin2b   = (const float*)d_in[17];
    const float* linw    = (const float*)d_in[18];
    const float* linb    = (const float*)d_in[19];
    float* outp = (float*)d_out;

    const int smI = 110592;   // occupancy 2
    const int smN = 75776;    // occupancy 3

    cudaFuncSetAttribute(k_edge<0>, cudaFuncAttributeMaxDynamicSharedMemorySize, smI);
    cudaFuncSetAttribute(k_edge<1>, cudaFuncAttributeMaxDynamicSharedMemorySize, smN);
    cudaFuncSetAttribute(k_nodeNE,  cudaFuncAttributeMaxDynamicSharedMemorySize, NSM_TOTAL);
    cudaFuncSetAttribute(k_nodeL,   cudaFuncAttributeMaxDynamicSharedMemorySize, NSM_TOTAL);

    // ---- sort edges by destination + precompute per-edge data ----
    k_zero_cnt<<<NN / 256, 256>>>();
    k_hist<<<EE / 256, 256>>>(ei);
    k_scan<<<1, 1024>>>();
    k_place<<<EE / 256, 256>>>(ei);
    k_build<<<EE / 8, 256>>>(ei, ew, means, betas);
    k_gather<<<NN * HID / 256, 256>>>(z, emb, neemb);

    // ---- weight prep ----
    k_wprep1<<<(NLAY * HID * K1 + 255) / 256, 256>>>(mlpw1, 0, NLAY);
    k_wprep1<<<(HID * K1 + 255) / 256, 256>>>(neprojw, 1, 1);
    k_wprep2<<<(NLAY * HID * HID + 255) / 256, 256>>>(mlpw2);
    k_wprepAll<<<NSLOT * 64, 256>>>(necatw, lin1w, lin2w, linw);

    // ---- NeighborEmbedding + initial lin1 ----
    k_edge<1><<<444, 256, smN>>>(0, neprojb, nullptr);
    k_nodeNE<<<NN / 64, 256, NSM_TOTAL>>>(necatb);

    // ---- interaction layers ----
    for (int l = 0; l < NLAY; l++) {
        k_edge<0><<<296, 256, smI>>>(l, mlpb1 + (size_t)l * HID, mlpb2 + (size_t)l * HID);
        k_nodeL<<<NN / 64, 256, NSM_TOTAL>>>(l, l == NLAY - 1,
                                             lin2b + (size_t)l * HID,
                                             linb + (size_t)l * HID, outp);
    }
}

// round 17
// speedup vs baseline: 1.1309x; 1.1309x over previous
#include <cuda_runtime.h>
#include <cuda_fp16.h>
#include <math.h>

// ---------------- problem constants ----------------
#define NN    8192
#define EE    262144
#define HID   128
#define NRBF  50
#define K1    64
#define NLAY  6
#define PR    72           // smem pitch (fp16) for rbf / W1^T
#define PT    136          // smem pitch (fp16) for T / W2^T / node tiles
#define PG    132          // smem pitch (fp16) for F / Hstage in edge kernel
#define NSLOT 20

typedef __half  h16;
typedef __half2 h162;

// ---------------- device scratch ----------------
__device__ __align__(16) h16 g_rbf[(size_t)EE * K1];
__device__ __align__(16) h16 g_w1t[NLAY * HID * K1];
__device__ __align__(16) h16 g_w2t[NLAY * HID * HID];
__device__ __align__(16) h16 g_npt[HID * K1];
__device__ __align__(16) h16 g_nwt[NSLOT * HID * HID];
__device__ __align__(16) h16 g_h16 [NN * HID];
__device__ __align__(16) h16 g_nex16[NN * HID];
__device__ float g_cut[EE];
__device__ float g_cutm[EE];
__device__ int   g_srow[EE];
__device__ int   g_sdst[EE];
__device__ int   g_perm[EE];
__device__ int   g_cnt[NN];
__device__ int   g_offm[NN];
__device__ float g_x  [NN * HID];
__device__ float g_agg[NN * HID];

// ---------------- small helper kernels ----------------
__global__ void k_zero_cnt() {
    int i = blockIdx.x * blockDim.x + threadIdx.x;
    if (i < NN) g_cnt[i] = 0;
}

__global__ void k_hist(const int* __restrict__ ei) {
    int e = blockIdx.x * blockDim.x + threadIdx.x;
    if (e < EE) atomicAdd(&g_cnt[ei[EE + e]], 1);
}

__global__ void k_scan() {
    __shared__ int part[1024];
    int t = threadIdx.x;
    int base = t * 8;
    int loc[8];
    int s = 0;
#pragma unroll
    for (int i = 0; i < 8; i++) { loc[i] = s; s += g_cnt[base + i]; }
    part[t] = s;
    __syncthreads();
    int val = s;
    for (int off = 1; off < 1024; off <<= 1) {
        int v = (t >= off) ? part[t - off] : 0;
        __syncthreads();
        val += v;
        part[t] = val;
        __syncthreads();
    }
    int pre = (t == 0) ? 0 : part[t - 1];
#pragma unroll
    for (int i = 0; i < 8; i++) g_offm[base + i] = pre + loc[i];
}

__global__ void k_place(const int* __restrict__ ei) {
    int e = blockIdx.x * blockDim.x + threadIdx.x;
    if (e < EE) {
        int c = ei[EE + e];
        int p = atomicAdd(&g_offm[c], 1);
        g_perm[p] = e;
    }
}

__global__ void k_build(const int* __restrict__ ei, const float* __restrict__ ew,
                        const float* __restrict__ means, const float* __restrict__ betas) {
    int warp = (blockIdx.x * blockDim.x + threadIdx.x) >> 5;
    int lane = threadIdx.x & 31;
    if (warp >= EE) return;
    int e = g_perm[warp];
    int r = ei[e];
    int c = ei[EE + e];
    float d = ew[e];
    float cut = 0.5f * (cosf(d * 0.628318530717958647692f) + 1.0f);
    if (!(d < 5.0f)) cut = 0.f;
    float ex = __expf(-d);
    size_t ro = (size_t)warp * K1;
    {
        float m = means[lane], b = betas[lane];
        float v = ex - m;
        g_rbf[ro + lane] = __float2half_rn(cut * __expf(-b * v * v));
    }
    int k2 = lane + 32;
    float val2 = 0.f;
    if (k2 < NRBF) {
        float m = means[k2], b = betas[k2];
        float v = ex - m;
        val2 = cut * __expf(-b * v * v);
    }
    g_rbf[ro + k2] = __float2half_rn(val2);
    if (lane == 0) {
        g_cut[warp]  = cut;
        g_cutm[warp] = (r != c) ? cut : 0.f;
        g_srow[warp] = r;
        g_sdst[warp] = c;
    }
}

__global__ void k_gather(const int* __restrict__ z, const float* __restrict__ emb,
                         const float* __restrict__ neemb) {
    int i = blockIdx.x * blockDim.x + threadIdx.x;
    if (i >= NN * HID) return;
    int n = i >> 7, c = i & 127;
    int zi = z[n];
    g_x[i]     = emb[zi * HID + c];
    g_nex16[i] = __float2half_rn(neemb[zi * HID + c]);
    g_agg[i]   = 0.f;
}

// weight prep (single fp16, transposed)
__global__ void k_wprep1(const float* __restrict__ w, int mode, int layers) {
    int i = blockIdx.x * blockDim.x + threadIdx.x;
    if (i >= layers * HID * K1) return;
    int k = i & (K1 - 1);
    int n = (i >> 6) & (HID - 1);
    int l = i >> 13;
    float v = (k < NRBF) ? w[((size_t)l * NRBF + k) * HID + n] : 0.f;
    if (mode == 0) g_w1t[i] = __float2half_rn(v);
    else           g_npt[i] = __float2half_rn(v);
}

__global__ void k_wprep2(const float* __restrict__ w) {
    int i = blockIdx.x * blockDim.x + threadIdx.x;
    if (i >= NLAY * HID * HID) return;
    int k = i & (HID - 1);
    int n = (i >> 7) & (HID - 1);
    int l = i >> 14;
    g_w2t[i] = __float2half_rn(w[((size_t)l * HID + k) * HID + n]);
}

__global__ void k_wprepAll(const float* __restrict__ necatw, const float* __restrict__ lin1w,
                           const float* __restrict__ lin2w, const float* __restrict__ linw) {
    int slot = blockIdx.x >> 6;
    int i = (blockIdx.x & 63) * 256 + threadIdx.x;
    const float* src;
    if (slot < 2)       src = necatw + (size_t)slot * HID * HID;
    else if (slot < 8)  src = lin1w + (size_t)(slot - 2) * HID * HID;
    else if (slot < 14) src = lin2w + (size_t)(slot - 8) * HID * HID;
    else                src = linw  + (size_t)(slot - 14) * HID * HID;
    int k = i & (HID - 1);
    int n = i >> 7;
    g_nwt[(size_t)slot * HID * HID + i] = __float2half_rn(src[k * HID + n]);
}

// ---------------- warp-MMA helpers (fp16) ----------------
__device__ __forceinline__ void mma16816(float c[4], const unsigned a[4], const unsigned b[2]) {
    asm volatile(
        "mma.sync.aligned.m16n8k16.row.col.f32.f16.f16.f32 "
        "{%0,%1,%2,%3}, {%4,%5,%6,%7}, {%8,%9}, {%0,%1,%2,%3};\n"
        : "+f"(c[0]), "+f"(c[1]), "+f"(c[2]), "+f"(c[3])
        : "r"(a[0]), "r"(a[1]), "r"(a[2]), "r"(a[3]), "r"(b[0]), "r"(b[1]));
}

__device__ __forceinline__ void ldsm4(unsigned r[4], unsigned addr) {
    asm volatile("ldmatrix.sync.aligned.m8n8.x4.shared.b16 {%0,%1,%2,%3}, [%4];"
        : "=r"(r[0]), "=r"(r[1]), "=r"(r[2]), "=r"(r[3]) : "r"(addr));
}

__device__ __forceinline__ unsigned a_addr(unsigned base, int m0, int PB, int lane) {
    int sel = lane >> 3, li = lane & 7;
    return base + (m0 + li + (sel & 1) * 8) * PB + ((sel >> 1) * 8) * 2;
}
__device__ __forceinline__ unsigned b_addr(unsigned base, int n0, int PB, int lane) {
    int sel = lane >> 3, li = lane & 7;
    return base + (n0 + li + (sel >> 1) * 8) * PB + ((sel & 1) * 8) * 2;
}

// 32x32 warp GEMM: acc += A*B; both single fp16
template <int KSTEPS, int PB>
__device__ __forceinline__ void wgemm1(unsigned aA, unsigned bB, float acc[2][4][4]) {
#pragma unroll
    for (int ks = 0; ks < KSTEPS; ks++) {
        unsigned off = ks * 32;
        unsigned a0[4], a1[4], b0[4], b1[4];
        ldsm4(a0, aA + off);
        ldsm4(a1, aA + 16 * PB + off);
        ldsm4(b0, bB + off);
        ldsm4(b1, bB + 16 * PB + off);
#pragma unroll
        for (int nt = 0; nt < 4; nt++) {
            const unsigned* bp = (nt < 2) ? (b0 + 2 * nt) : (b1 + 2 * (nt - 2));
            mma16816(acc[0][nt], a0, bp);
            mma16816(acc[1][nt], a1, bp);
        }
    }
}

// ---------------- cp.async helpers ----------------
__device__ __forceinline__ void cpa16(unsigned saddr, const void* gaddr) {
    asm volatile("cp.async.ca.shared.global [%0], [%1], 16;" :: "r"(saddr), "l"(gaddr));
}
__device__ __forceinline__ void cpa8(unsigned saddr, const void* gaddr) {
    asm volatile("cp.async.ca.shared.global [%0], [%1], 8;" :: "r"(saddr), "l"(gaddr));
}
__device__ __forceinline__ void cpa_commit() { asm volatile("cp.async.commit_group;"); }
__device__ __forceinline__ void cpa_wait0()  { asm volatile("cp.async.wait_group 0;"); }
__device__ __forceinline__ void cpa_wait1()  { asm volatile("cp.async.wait_group 1;"); }

__device__ __forceinline__ float fsilu(float x) {
    return __fdividef(x, 1.f + __expf(-x));
}

// ---------------- fused edge MLP + segmented aggregation (persistent) --------
// rbf double-buffered; Hstage issued at tile start; race-safe wait->barrier.
// interaction smem: T[0,34816) W2[34816) rbf0[69632) rbf1[88064) W1[106496)
//   H16[124928,+33792) F16[158720,+33792) misc[192512,+4096) = 196608
// NE smem: F16[0,33792) rbf0[33792) rbf1[52224) W1[70656) H16[89088,+33792)
//   misc[122880,+4096) = 126976
template <int NE>
__global__ void __launch_bounds__(512, 1)
k_edge(int layer, const float* __restrict__ b1g, const float* __restrict__ b2g) {
    extern __shared__ __align__(16) char smref[];
    constexpr int R_BYTES = HID * PR * 2;   // 18432
    const int OFF_T    = 0;                 // interaction only
    const int OFF_W2   = 34816;
    const int OFF_R0   = NE ? 33792 : 69632;
    const int OFF_W1   = OFF_R0 + 2 * R_BYTES;
    const int OFF_H    = OFF_W1 + R_BYTES;
    const int OFF_F    = NE ? 0 : (OFF_H + 33792);
    const int OFF_MISC = OFF_H + 33792 + (NE ? 0 : 33792);
    const int OFF_CUT  = OFF_MISC;          // [2][128] f32
    const int OFF_ROW  = OFF_MISC + 1024;   // [2][128] i32
    const int OFF_DST  = OFF_MISC + 2048;   // [2][128] i32
    const int OFF_B1   = OFF_MISC + 3072;
    const int OFF_B2   = OFF_MISC + 3584;

    h16*  sT   = (h16*)(smref + OFF_T);
    h16*  sF16 = (h16*)(smref + OFF_F);
    h16*  sH16 = (h16*)(smref + OFF_H);
    float* sB1 = (float*)(smref + OFF_B1);
    float* sB2 = (float*)(smref + OFF_B2);

    int tid = threadIdx.x;
    unsigned sbase = (unsigned)__cvta_generic_to_shared(smref);

    const long NT = EE / 128;
    long tile = blockIdx.x;
    int buf = 0;

    // priming: tile-0 rbf into slot 0 + metadata slot 0
    if (tile < NT) {
        long ebase = tile * 128;
        for (int c = tid; c < 1024; c += 512) {
            int r = c >> 3, ch = c & 7;
            cpa16(sbase + OFF_R0 + r * (PR * 2) + ch * 16, &g_rbf[(ebase + r) * K1 + ch * 8]);
        }
        if (tid < 32) {
            const float* cs = NE ? g_cutm : g_cut;
            cpa16(sbase + OFF_CUT + tid * 16, cs + ebase + tid * 4);
        } else if (tid < 64) {
            int t = tid - 32;
            cpa16(sbase + OFF_ROW + t * 16, g_srow + ebase + t * 4);
        } else if (tid < 96) {
            int t = tid - 64;
            cpa16(sbase + OFF_DST + t * 16, g_sdst + ebase + t * 4);
        }
    }
    cpa_commit();

    // ---- stage weights once ----
    {
        const unsigned* gw = (const unsigned*)(NE ? g_npt : (g_w1t + (size_t)layer * HID * K1));
        unsigned* sw = (unsigned*)(smref + OFF_W1);
        for (int i = tid; i < 128 * 32; i += 512) {
            int r = i >> 5, wd = i & 31;
            sw[r * (PR / 2) + wd] = gw[i];
        }
    }
    if (!NE) {
        const unsigned* gw = (const unsigned*)(g_w2t + (size_t)layer * HID * HID);
        unsigned* sw = (unsigned*)(smref + OFF_W2);
        for (int i = tid; i < 128 * 64; i += 512) {
            int r = i >> 6, wd = i & 63;
            sw[r * (PT / 2) + wd] = gw[i];
        }
    }
    if (tid < 128) {
        sB1[tid] = b1g[tid];
        sB2[tid] = NE ? 0.f : b2g[tid];
    }

    int w = tid >> 5, lane = tid & 31;
    int m0 = (w & 3) * 32, n0 = (w >> 2) * 32;
    int g = lane >> 2, tc = lane & 3;

    unsigned g1aA[2];
    g1aA[0] = a_addr(sbase + OFF_R0,           m0, PR * 2, lane);
    g1aA[1] = a_addr(sbase + OFF_R0 + R_BYTES, m0, PR * 2, lane);
    unsigned g1b = b_addr(sbase + OFF_W1, n0, PR * 2, lane);
    unsigned g2a = a_addr(sbase + OFF_T,  m0, PT * 2, lane);
    unsigned g2b = b_addr(sbase + OFF_W2, n0, PT * 2, lane);

    const h16* hsrc = NE ? g_nex16 : g_h16;

    for (; tile < NT; tile += gridDim.x, buf ^= 1) {
        cpa_wait0();
        __syncthreads();   // rbf[buf] + meta[buf] fully landed; prev tile consumed

        float* sCut = (float*)(smref + OFF_CUT + buf * 512);
        int*   sRow = (int*)(smref + OFF_ROW + buf * 512);
        int*   sDst = (int*)(smref + OFF_DST + buf * 512);

        // ---- issue Hstage (group H) — overlaps both GEMMs ----
        for (int i = tid; i < 4096; i += 512) {
            int e = i >> 5, ch = i & 31;
            cpa8(sbase + OFF_H + e * (PG * 2) + ch * 8,
                 hsrc + (long)sRow[e] * HID + ch * 4);
        }
        cpa_commit();

        // ---- issue next tile's rbf + meta into slot buf^1 (group R) ----
        {
            long nxt = tile + gridDim.x;
            if (nxt < NT) {
                long ebase = nxt * 128;
                int nb = buf ^ 1;
                for (int c = tid; c < 1024; c += 512) {
                    int r = c >> 3, ch = c & 7;
                    cpa16(sbase + OFF_R0 + nb * R_BYTES + r * (PR * 2) + ch * 16,
                          &g_rbf[(ebase + r) * K1 + ch * 8]);
                }
                if (tid < 32) {
                    const float* cs = NE ? g_cutm : g_cut;
                    cpa16(sbase + OFF_CUT + nb * 512 + tid * 16, cs + ebase + tid * 4);
                } else if (tid < 64) {
                    int t = tid - 32;
                    cpa16(sbase + OFF_ROW + nb * 512 + t * 16, g_srow + ebase + t * 4);
                } else if (tid < 96) {
                    int t = tid - 64;
                    cpa16(sbase + OFF_DST + nb * 512 + t * 16, g_sdst + ebase + t * 4);
                }
            }
            cpa_commit();
        }

        // ---- GEMM1: rbf[128,64] @ W1[64,128] ----
        {
            float acc[2][4][4];
#pragma unroll
            for (int a = 0; a < 2; a++)
#pragma unroll
                for (int b = 0; b < 4; b++)
#pragma unroll
                    for (int c = 0; c < 4; c++) acc[a][b][c] = 0.f;
            wgemm1<K1 / 16, PR * 2>(g1aA[buf], g1b, acc);

            if (NE) {
                // F = (acc + b1) * cutm -> fp16 F
#pragma unroll
                for (int mt = 0; mt < 2; mt++) {
                    int ra = m0 + mt * 16 + g, rb2 = ra + 8;
                    float cua = sCut[ra], cub = sCut[rb2];
#pragma unroll
                    for (int nt = 0; nt < 4; nt++) {
                        int col = n0 + nt * 8 + 2 * tc;
                        *(h162*)&sF16[ra * PG + col] = __floats2half2_rn(
                            (acc[mt][nt][0] + sB1[col]) * cua,
                            (acc[mt][nt][1] + sB1[col + 1]) * cua);
                        *(h162*)&sF16[rb2 * PG + col] = __floats2half2_rn(
                            (acc[mt][nt][2] + sB1[col]) * cub,
                            (acc[mt][nt][3] + sB1[col + 1]) * cub);
                    }
                }
            } else {
                // T = silu(acc + b1) -> fp16 T
#pragma unroll
                for (int mt = 0; mt < 2; mt++) {
                    int ra = m0 + mt * 16 + g, rb2 = ra + 8;
#pragma unroll
                    for (int nt = 0; nt < 4; nt++) {
                        int col = n0 + nt * 8 + 2 * tc;
                        float x0 = fsilu(acc[mt][nt][0] + sB1[col]);
                        float x1 = fsilu(acc[mt][nt][1] + sB1[col + 1]);
                        float x2 = fsilu(acc[mt][nt][2] + sB1[col]);
                        float x3 = fsilu(acc[mt][nt][3] + sB1[col + 1]);
                        *(h162*)&sT[ra * PT + col]  = __floats2half2_rn(x0, x1);
                        *(h162*)&sT[rb2 * PT + col] = __floats2half2_rn(x2, x3);
                    }
                }
            }
        }

        // ---- GEMM2 (interaction only): needs cross-warp T -> barrier ----
        if (!NE) {
            __syncthreads();   // T visible to all warps
            float acc[2][4][4];
#pragma unroll
            for (int a = 0; a < 2; a++)
#pragma unroll
                for (int b = 0; b < 4; b++)
#pragma unroll
                    for (int c = 0; c < 4; c++) acc[a][b][c] = 0.f;
            wgemm1<HID / 16, PT * 2>(g2a, g2b, acc);
#pragma unroll
            for (int mt = 0; mt < 2; mt++) {
                int ra = m0 + mt * 16 + g, rb2 = ra + 8;
                float cua = sCut[ra], cub = sCut[rb2];
#pragma unroll
                for (int nt = 0; nt < 4; nt++) {
                    int col = n0 + nt * 8 + 2 * tc;
                    *(h162*)&sF16[ra * PG + col] = __floats2half2_rn(
                        (acc[mt][nt][0] + sB2[col]) * cua,
                        (acc[mt][nt][1] + sB2[col + 1]) * cua);
                    *(h162*)&sF16[rb2 * PG + col] = __floats2half2_rn(
                        (acc[mt][nt][2] + sB2[col]) * cub,
                        (acc[mt][nt][3] + sB2[col + 1]) * cub);
                }
            }
        }

        // ---- own-H wait, then barrier: F + all threads' Hstage visible ----
        cpa_wait1();
        __syncthreads();

        // ---- aggregation: 8 groups x 64 threads, channel pair, 16 edges ----
        int grp = tid >> 6;
        int f2 = tid & 63;
        int c0 = 2 * f2;
        int e0 = grp * 16;
        float a0 = 0.f, a1 = 0.f;
        int cur = sDst[e0];
#pragma unroll 4
        for (int j = 0; j < 16; j++) {
            int e = e0 + j;
            int dd = sDst[e];
            if (dd != cur) {
                atomicAdd(&g_agg[(long)cur * HID + c0], a0);
                atomicAdd(&g_agg[(long)cur * HID + c0 + 1], a1);
                a0 = a1 = 0.f;
                cur = dd;
            }
            float2 hf = __half22float2(*(const h162*)&sH16[e * PG + c0]);
            float2 ff = __half22float2(*(const h162*)&sF16[e * PG + c0]);
            a0 = fmaf(hf.x, ff.x, a0);
            a1 = fmaf(hf.y, ff.y, a1);
        }
        atomicAdd(&g_agg[(long)cur * HID + c0], a0);
        atomicAdd(&g_agg[(long)cur * HID + c0 + 1], a1);
    }
}

// ---------------- node-kernel shared pieces (R14, unchanged) -----------------
#define NA_BYTES  (64 * PT * 2)
#define NW_BYTES  (HID * PT * 2)
#define NOFF_A    0
#define NOFF_WA   NA_BYTES
#define NOFF_WB   (NOFF_WA + NW_BYTES)
#define NOFF_H    (NOFF_WB + NW_BYTES)
#define NOFF_B    (NOFF_H + NA_BYTES)
#define NSM_TOTAL (NOFF_B + 1024)

__device__ __forceinline__ void stageA_f16(char* smref, int off, const float* src,
                                           int rb, int tid) {
    h16* dst = (h16*)(smref + off);
    for (int i = tid; i < 64 * HID; i += 256) {
        int r = i >> 7, k = i & 127;
        dst[r * PT + k] = __float2half_rn(src[(long)(rb + r) * HID + k]);
    }
}

__device__ __forceinline__ void stageW(char* smref, int off, int slot, int tid) {
    const unsigned* gw = (const unsigned*)(g_nwt + (size_t)slot * HID * HID);
    unsigned* sw = (unsigned*)(smref + off);
    for (int i = tid; i < 128 * 64; i += 256) {
        int r = i >> 6, wd = i & 63;
        sw[r * (PT / 2) + wd] = gw[i];
    }
}

__global__ void __launch_bounds__(256, 1)
k_nodeNE(const float* __restrict__ necatb) {
    extern __shared__ __align__(16) char smref[];
    float* sBa = (float*)(smref + NOFF_B);

    int tid = threadIdx.x;
    int rb = blockIdx.x * 64;
    unsigned sbase = (unsigned)__cvta_generic_to_shared(smref);

    stageA_f16(smref, NOFF_A, g_x, rb, tid);
    stageW(smref, NOFF_WA, 0, tid);
    stageW(smref, NOFF_WB, 1, tid);
    if (tid < 128) sBa[tid] = necatb[tid];
    __syncthreads();

    int w = tid >> 5, lane = tid & 31;
    int m0 = (w & 1) * 32, n0 = (w >> 1) * 32;
    int g = lane >> 2, tc = lane & 3;

    float acc[2][4][4];
#pragma unroll
    for (int a = 0; a < 2; a++)
#pragma unroll
        for (int b = 0; b < 4; b++)
#pragma unroll
            for (int c = 0; c < 4; c++) acc[a][b][c] = 0.f;

    {
        unsigned aA = a_addr(sbase + NOFF_A, m0, PT * 2, lane);
        unsigned bB = b_addr(sbase + NOFF_WA, n0, PT * 2, lane);
        wgemm1<HID / 16, PT * 2>(aA, bB, acc);
    }
    __syncthreads();

    stageA_f16(smref, NOFF_A, g_agg, rb, tid);
    stageW(smref, NOFF_WA, 2, tid);
    __syncthreads();

    {
        float4* za = (float4*)(g_agg + (long)rb * HID);
        for (int i = tid; i < 64 * HID / 4; i += 256) za[i] = make_float4(0.f, 0.f, 0.f, 0.f);
    }

    {
        unsigned aA = a_addr(sbase + NOFF_A, m0, PT * 2, lane);
        unsigned bB = b_addr(sbase + NOFF_WB, n0, PT * 2, lane);
        wgemm1<HID / 16, PT * 2>(aA, bB, acc);

        h16* xh = (h16*)(smref + NOFF_H);
#pragma unroll
        for (int mt = 0; mt < 2; mt++) {
#pragma unroll
            for (int dr = 0; dr < 2; dr++) {
                int r = m0 + mt * 16 + g + dr * 8;
                long ro = (long)(rb + r) * HID;
#pragma unroll
                for (int nt = 0; nt < 4; nt++) {
                    int col = n0 + nt * 8 + 2 * tc;
                    float v0 = acc[mt][nt][2 * dr]     + sBa[col];
                    float v1 = acc[mt][nt][2 * dr + 1] + sBa[col + 1];
                    *(float2*)&g_x[ro + col] = make_float2(v0, v1);
                    *(h162*)&xh[r * PT + col] = __floats2half2_rn(v0, v1);
                }
            }
        }
    }
    __syncthreads();

    {
        float acc2[2][4][4];
#pragma unroll
        for (int a = 0; a < 2; a++)
#pragma unroll
            for (int b = 0; b < 4; b++)
#pragma unroll
                for (int c = 0; c < 4; c++) acc2[a][b][c] = 0.f;
        unsigned aA = a_addr(sbase + NOFF_H, m0, PT * 2, lane);
        unsigned bB = b_addr(sbase + NOFF_WA, n0, PT * 2, lane);
        wgemm1<HID / 16, PT * 2>(aA, bB, acc2);
#pragma unroll
        for (int mt = 0; mt < 2; mt++) {
#pragma unroll
            for (int dr = 0; dr < 2; dr++) {
                int r = m0 + mt * 16 + g + dr * 8;
                long ro = (long)(rb + r) * HID;
#pragma unroll
                for (int nt = 0; nt < 4; nt++) {
                    int col = n0 + nt * 8 + 2 * tc;
                    *(h162*)&g_h16[ro + col] =
                        __floats2half2_rn(acc2[mt][nt][2 * dr], acc2[mt][nt][2 * dr + 1]);
                }
            }
        }
    }
}

__global__ void __launch_bounds__(256, 1)
k_nodeL(int l, int last, const float* __restrict__ b2g, const float* __restrict__ b3g,
        float* dout) {
    extern __shared__ __align__(16) char smref[];
    float* sB2 = (float*)(smref + NOFF_B);
    float* sB3 = sB2 + 128;

    int tid = threadIdx.x;
    int rb = blockIdx.x * 64;
    unsigned sbase = (unsigned)__cvta_generic_to_shared(smref);

    stageA_f16(smref, NOFF_A, g_agg, rb, tid);
    stageW(smref, NOFF_WA, 8 + l, tid);
    stageW(smref, NOFF_WB, 14 + l, tid);
    if (tid < 128) { sB2[tid] = b2g[tid]; sB3[tid] = b3g[tid]; }
    __syncthreads();

    int w = tid >> 5, lane = tid & 31;
    int m0 = (w & 1) * 32, n0 = (w >> 1) * 32;
    int g = lane >> 2, tc = lane & 3;

    {
        float acc[2][4][4];
#pragma unroll
        for (int a = 0; a < 2; a++)
#pragma unroll
            for (int b = 0; b < 4; b++)
#pragma unroll
                for (int c = 0; c < 4; c++) acc[a][b][c] = 0.f;
        unsigned aA = a_addr(sbase + NOFF_A, m0, PT * 2, lane);
        unsigned bB = b_addr(sbase + NOFF_WA, n0, PT * 2, lane);
        wgemm1<HID / 16, PT * 2>(aA, bB, acc);

        h16* sHn = (h16*)(smref + NOFF_H);
#pragma unroll
        for (int mt = 0; mt < 2; mt++) {
            int ra = m0 + mt * 16 + g, rb2 = ra + 8;
#pragma unroll
            for (int nt = 0; nt < 4; nt++) {
                int col = n0 + nt * 8 + 2 * tc;
                float x0 = fsilu(acc[mt][nt][0] + sB2[col]);
                float x1 = fsilu(acc[mt][nt][1] + sB2[col + 1]);
                float x2 = fsilu(acc[mt][nt][2] + sB2[col]);
                float x3 = fsilu(acc[mt][nt][3] + sB2[col + 1]);
                *(h162*)&sHn[ra * PT + col]  = __floats2half2_rn(x0, x1);
                *(h162*)&sHn[rb2 * PT + col] = __floats2half2_rn(x2, x3);
            }
        }
    }
    __syncthreads();

    if (!last) {
        stageW(smref, NOFF_WA, 2 + (l + 1), tid);
        float4* za = (float4*)(g_agg + (long)rb * HID);
        for (int i = tid; i < 64 * HID / 4; i += 256) za[i] = make_float4(0.f, 0.f, 0.f, 0.f);
    }

    {
        float acc[2][4][4];
#pragma unroll
        for (int a = 0; a < 2; a++)
#pragma unroll
            for (int b = 0; b < 4; b++)
#pragma unroll
                for (int c = 0; c < 4; c++) acc[a][b][c] = 0.f;
        unsigned aA = a_addr(sbase + NOFF_H, m0, PT * 2, lane);
        unsigned bB = b_addr(sbase + NOFF_WB, n0, PT * 2, lane);
        wgemm1<HID / 16, PT * 2>(aA, bB, acc);

        float* out = last ? dout : g_x;
        h16* xh = (h16*)(smref + NOFF_A);
#pragma unroll
        for (int mt = 0; mt < 2; mt++) {
#pragma unroll
            for (int dr = 0; dr < 2; dr++) {
                int r = m0 + mt * 16 + g + dr * 8;
                long ro = (long)(rb + r) * HID;
#pragma unroll
                for (int nt = 0; nt < 4; nt++) {
                    int col = n0 + nt * 8 + 2 * tc;
                    float v0 = acc[mt][nt][2 * dr]     + sB3[col] + g_x[ro + col];
                    float v1 = acc[mt][nt][2 * dr + 1] + sB3[col + 1] + g_x[ro + col + 1];
                    *(float2*)&out[ro + col] = make_float2(v0, v1);
                    if (!last)
                        *(h162*)&xh[r * PT + col] = __floats2half2_rn(v0, v1);
                }
            }
        }
    }
    if (last) return;
    __syncthreads();

    {
        float acc[2][4][4];
#pragma unroll
        for (int a = 0; a < 2; a++)
#pragma unroll
            for (int b = 0; b < 4; b++)
#pragma unroll
                for (int c = 0; c < 4; c++) acc[a][b][c] = 0.f;
        unsigned aA = a_addr(sbase + NOFF_A, m0, PT * 2, lane);
        unsigned bB = b_addr(sbase + NOFF_WA, n0, PT * 2, lane);
        wgemm1<HID / 16, PT * 2>(aA, bB, acc);
#pragma unroll
        for (int mt = 0; mt < 2; mt++) {
#pragma unroll
            for (int dr = 0; dr < 2; dr++) {
                int r = m0 + mt * 16 + g + dr * 8;
                long ro = (long)(rb + r) * HID;
#pragma unroll
                for (int nt = 0; nt < 4; nt++) {
                    int col = n0 + nt * 8 + 2 * tc;
                    *(h162*)&g_h16[ro + col] =
                        __floats2half2_rn(acc[mt][nt][2 * dr], acc[mt][nt][2 * dr + 1]);
                }
            }
        }
    }
}

// ---------------- launch ----------------
extern "C" void kernel_launch(void* const* d_in, const int* in_sizes, int n_in,
                              void* d_out, int out_size) {
    const int*   z       = (const int*)d_in[0];
    const int*   ei      = (const int*)d_in[1];
    const float* ew      = (const float*)d_in[2];
    const float* emb     = (const float*)d_in[3];
    const float* neemb   = (const float*)d_in[4];
    const float* neprojw = (const float*)d_in[5];
    const float* neprojb = (const float*)d_in[6];
    const float* necatw  = (const float*)d_in[7];
    const float* necatb  = (const float*)d_in[8];
    const float* means   = (const float*)d_in[9];
    const float* betas   = (const float*)d_in[10];
    const float* mlpw1   = (const float*)d_in[11];
    const float* mlpb1   = (const float*)d_in[12];
    const float* mlpw2   = (const float*)d_in[13];
    const float* mlpb2   = (const float*)d_in[14];
    const float* lin1w   = (const float*)d_in[15];
    const float* lin2w   = (const float*)d_in[16];
    const float* lin2b   = (const float*)d_in[17];
    const float* linw    = (const float*)d_in[18];
    const float* linb    = (const float*)d_in[19];
    float* outp = (float*)d_out;

    const int smI = 196608;   // interaction edge (occ 1)
    const int smN = 126976;   // NE edge

    cudaFuncSetAttribute(k_edge<0>, cudaFuncAttributeMaxDynamicSharedMemorySize, smI);
    cudaFuncSetAttribute(k_edge<1>, cudaFuncAttributeMaxDynamicSharedMemorySize, smN);
    cudaFuncSetAttribute(k_nodeNE,  cudaFuncAttributeMaxDynamicSharedMemorySize, NSM_TOTAL);
    cudaFuncSetAttribute(k_nodeL,   cudaFuncAttributeMaxDynamicSharedMemorySize, NSM_TOTAL);

    // ---- sort edges by destination + precompute per-edge data ----
    k_zero_cnt<<<NN / 256, 256>>>();
    k_hist<<<EE / 256, 256>>>(ei);
    k_scan<<<1, 1024>>>();
    k_place<<<EE / 256, 256>>>(ei);
    k_build<<<EE / 8, 256>>>(ei, ew, means, betas);
    k_gather<<<NN * HID / 256, 256>>>(z, emb, neemb);

    // ---- weight prep ----
    k_wprep1<<<(NLAY * HID * K1 + 255) / 256, 256>>>(mlpw1, 0, NLAY);
    k_wprep1<<<(HID * K1 + 255) / 256, 256>>>(neprojw, 1, 1);
    k_wprep2<<<(NLAY * HID * HID + 255) / 256, 256>>>(mlpw2);
    k_wprepAll<<<NSLOT * 64, 256>>>(necatw, lin1w, lin2w, linw);

    // ---- NeighborEmbedding + initial lin1 ----
    k_edge<1><<<148, 512, smN>>>(0, neprojb, nullptr);
    k_nodeNE<<<NN / 64, 256, NSM_TOTAL>>>(necatb);

    // ---- interaction layers ----
    for (int l = 0; l < NLAY; l++) {
        k_edge<0><<<148, 512, smI>>>(l, mlpb1 + (size_t)l * HID, mlpb2 + (size_t)l * HID);
        k_nodeL<<<NN / 64, 256, NSM_TOTAL>>>(l, l == NLAY - 1,
                                             lin2b + (size_t)l * HID,
                                             linb + (size_t)l * HID, outp);
    }
}